// round 1
// baseline (speedup 1.0000x reference)
#include <cuda_runtime.h>
#include <math.h>

// ---------------- problem constants ----------------
#define B_    4
#define S_    2048
#define H_    768
#define NH_   8
#define DH_   96
#define L_    128
#define ML_   15
#define LM_   1920      // L_*ML_
#define QKV_  2304      // 3*H_

// ---------------- scratch (static device globals; no allocation) ----------------
__device__ float g_qkv  [(size_t)B_ * S_  * QKV_];   // [B,S,3H] QKV of every token
__device__ float g_attn [(size_t)B_ * LM_ * H_];     // attention output (pre out_proj)
__device__ float g_oproj[(size_t)B_ * LM_ * H_];     // after out_proj
__device__ float g_x    [(size_t)B_ * L_ * 2 * H_];  // pooled [line_mean, attn_mean]
__device__ float g_y1   [(size_t)B_ * L_ * H_];
__device__ float g_y2   [(size_t)B_ * L_ * H_];

// ---------------- generic NT SGEMM: C[M,N] = A[M,K] @ B[N,K]^T + bias ----------------
// M,N multiples of 64, K multiple of 16 (true for every call here).
#define BM 64
#define BN 64
#define BK 16
__global__ __launch_bounds__(256) void sgemm_nt(
    const float* __restrict__ A, const float* __restrict__ Bw,
    const float* __restrict__ bias, float* __restrict__ C,
    int M, int N, int K)
{
    __shared__ float As[BK][BM + 1];
    __shared__ float Bs[BK][BN + 1];
    int tid = threadIdx.x;
    int tx = tid & 15, ty = tid >> 4;
    int m0 = blockIdx.y * BM, n0 = blockIdx.x * BN;
    float acc[4][4] = {};

    for (int k0 = 0; k0 < K; k0 += BK) {
#pragma unroll
        for (int i = 0; i < 4; i++) {
            int idx = tid + i * 256;
            int r = idx >> 4, c = idx & 15;            // r: 0..63, c: 0..15
            As[c][r] = A [(size_t)(m0 + r) * K + k0 + c];
            Bs[c][r] = Bw[(size_t)(n0 + r) * K + k0 + c];
        }
        __syncthreads();
#pragma unroll
        for (int kk = 0; kk < BK; kk++) {
            float a[4], b[4];
#pragma unroll
            for (int i = 0; i < 4; i++) a[i] = As[kk][ty + 16 * i];
#pragma unroll
            for (int j = 0; j < 4; j++) b[j] = Bs[kk][tx + 16 * j];
#pragma unroll
            for (int i = 0; i < 4; i++)
#pragma unroll
                for (int j = 0; j < 4; j++)
                    acc[i][j] += a[i] * b[j];
        }
        __syncthreads();
    }
#pragma unroll
    for (int j = 0; j < 4; j++) {
        float bj = bias ? bias[n0 + tx + 16 * j] : 0.0f;
#pragma unroll
        for (int i = 0; i < 4; i++)
            C[(size_t)(m0 + ty + 16 * i) * N + n0 + tx + 16 * j] = acc[i][j] + bj;
    }
}

// ---------------- flash-style cross attention ----------------
// grid: (LM_/QT, NH_, B_); block: 128 threads.
// Q = line tokens (gathered from qkv via line_starts), K/V = all context tokens.
#define QT   32
#define KT   64
#define PADQ 98   // even pad -> float2 smem loads stay 8B aligned + conflict-free
__global__ __launch_bounds__(128) void attn_kernel(
    const float* __restrict__ qkv,
    const int* __restrict__ line_starts,
    const int* __restrict__ line_lens,
    const int* __restrict__ ctx_len,
    float* __restrict__ out)
{
    __shared__ float Qs [QT][PADQ];
    __shared__ float KVs[KT][PADQ];      // K tile, then reused for V tile
    __shared__ float Ps [QT][KT + 1];
    __shared__ float m_s[QT], l_s[QT], fac_s[QT];

    int tid = threadIdx.x;
    int b = blockIdx.z, h = blockIdx.y, q0 = blockIdx.x * QT;
    int qg = tid >> 4, kg = tid & 15;    // 8 q-groups x 16 k-groups
    const float scale = 0.10206207261596577f; // 1/sqrt(96)

    // ---- load & scale Q tile (gathered line tokens) ----
    for (int idx = tid; idx < QT * DH_; idx += 128) {
        int r = idx / DH_, c = idx - r * DH_;
        int gq = q0 + r;
        int l  = gq / ML_;
        int m  = gq - l * ML_;
        int pos = line_starts[b * L_ + l] + m;
        pos = min(max(pos, 0), S_ - 1);
        Qs[r][c] = qkv[((size_t)b * S_ + pos) * QKV_ + h * DH_ + c] * scale;
    }
    if (tid < QT) { m_s[tid] = -3e38f; l_s[tid] = 0.0f; }
    int ctx = ctx_len[b];

    float Oacc[4][6];
#pragma unroll
    for (int i = 0; i < 4; i++)
#pragma unroll
        for (int j = 0; j < 6; j++) Oacc[i][j] = 0.0f;
    __syncthreads();

    for (int s0 = 0; s0 < S_; s0 += KT) {
        // ---- K tile ----
        for (int idx = tid; idx < KT * DH_; idx += 128) {
            int r = idx / DH_, c = idx - r * DH_;
            KVs[r][c] = qkv[((size_t)b * S_ + s0 + r) * QKV_ + H_ + h * DH_ + c];
        }
        __syncthreads();

        // ---- scores: thread computes 4q x 4k micro-tile (strided) ----
        float sc[4][4];
#pragma unroll
        for (int i = 0; i < 4; i++)
#pragma unroll
            for (int j = 0; j < 4; j++) sc[i][j] = 0.0f;
#pragma unroll 8
        for (int d = 0; d < DH_; d += 2) {
            float2 qa[4], kb[4];
#pragma unroll
            for (int i = 0; i < 4; i++) qa[i] = *(const float2*)&Qs[qg + 8 * i][d];
#pragma unroll
            for (int j = 0; j < 4; j++) kb[j] = *(const float2*)&KVs[kg + 16 * j][d];
#pragma unroll
            for (int i = 0; i < 4; i++)
#pragma unroll
                for (int j = 0; j < 4; j++) {
                    sc[i][j] += qa[i].x * kb[j].x;
                    sc[i][j] += qa[i].y * kb[j].y;
                }
        }
        // write (masked) scores to smem
#pragma unroll
        for (int i = 0; i < 4; i++)
#pragma unroll
            for (int j = 0; j < 4; j++) {
                int s = s0 + kg + 16 * j;
                Ps[qg + 8 * i][kg + 16 * j] = (s < ctx) ? sc[i][j] : -1e9f;
            }
        __syncthreads();   // all K reads + score writes done

        // ---- online softmax: one quad of lanes per query row ----
        {
            int row = tid >> 2, sub = tid & 3;
            float mx = -3e38f;
#pragma unroll
            for (int k = sub; k < KT; k += 4) mx = fmaxf(mx, Ps[row][k]);
            mx = fmaxf(mx, __shfl_xor_sync(0xffffffffu, mx, 1));
            mx = fmaxf(mx, __shfl_xor_sync(0xffffffffu, mx, 2));
            float mold = m_s[row];
            float mnew = fmaxf(mold, mx);
            float lsum = 0.0f;
#pragma unroll
            for (int k = sub; k < KT; k += 4) {
                float p = __expf(Ps[row][k] - mnew);
                Ps[row][k] = p;
                lsum += p;
            }
            lsum += __shfl_xor_sync(0xffffffffu, lsum, 1);
            lsum += __shfl_xor_sync(0xffffffffu, lsum, 2);
            if (sub == 0) {
                float f = __expf(mold - mnew);
                m_s[row]   = mnew;
                l_s[row]   = l_s[row] * f + lsum;
                fac_s[row] = f;
            }
        }
        // ---- V tile (overwrites K buffer; legal: K reads fenced above) ----
        for (int idx = tid; idx < KT * DH_; idx += 128) {
            int r = idx / DH_, c = idx - r * DH_;
            KVs[r][c] = qkv[((size_t)b * S_ + s0 + r) * QKV_ + 2 * H_ + h * DH_ + c];
        }
        __syncthreads();   // p-values, factors, V all ready

        // ---- rescale accumulators + P@V ----
        float f[4];
#pragma unroll
        for (int i = 0; i < 4; i++) f[i] = fac_s[qg + 8 * i];
#pragma unroll
        for (int i = 0; i < 4; i++)
#pragma unroll
            for (int j = 0; j < 6; j++) Oacc[i][j] *= f[i];
#pragma unroll 8
        for (int kk = 0; kk < KT; kk++) {
            float pv[4], vv[6];
#pragma unroll
            for (int i = 0; i < 4; i++) pv[i] = Ps[qg + 8 * i][kk];
#pragma unroll
            for (int j = 0; j < 6; j++) vv[j] = KVs[kk][kg + 16 * j];
#pragma unroll
            for (int i = 0; i < 4; i++)
#pragma unroll
                for (int j = 0; j < 6; j++)
                    Oacc[i][j] += pv[i] * vv[j];
        }
        __syncthreads();   // before next chunk overwrites KVs / Ps
    }

    // ---- epilogue: normalize, write [B, LM, H] ----
#pragma unroll
    for (int i = 0; i < 4; i++) {
        int q = qg + 8 * i;
        float inv = 1.0f / l_s[q];
        int gq = q0 + q;
#pragma unroll
        for (int j = 0; j < 6; j++)
            out[((size_t)b * LM_ + gq) * H_ + h * DH_ + kg + 16 * j] = Oacc[i][j] * inv;
    }
}

// ---------------- masked mean-pool over line tokens -> x=[line_mean, attn_mean] ----------------
__global__ __launch_bounds__(256) void pool_kernel(
    const float* __restrict__ hidden, const float* __restrict__ oproj,
    const int* __restrict__ line_starts, const int* __restrict__ line_lens,
    float* __restrict__ x)
{
    int bl = blockIdx.x;               // b*L + l
    int b = bl / L_;
    int len = line_lens[bl];
    int start = line_starts[bl];
    float inv = 1.0f / (float)max(len, 1);
    for (int c = threadIdx.x; c < H_; c += 256) {
        float s1 = 0.0f, s2 = 0.0f;
        for (int m = 0; m < ML_; m++) {
            if (m < len) {
                int pos = min(max(start + m, 0), S_ - 1);
                s1 += hidden[((size_t)b * S_ + pos) * H_ + c];
                s2 += oproj[((size_t)bl * ML_ + m) * H_ + c];
            }
        }
        x[(size_t)bl * 2 * H_ + c]       = s1 * inv;
        x[(size_t)bl * 2 * H_ + H_ + c]  = s2 * inv;
    }
}

// ---------------- rowwise LayerNorm -> exact GELU (+optional residual) ----------------
__global__ __launch_bounds__(256) void ln_gelu_kernel(
    const float* __restrict__ y, const float* __restrict__ g,
    const float* __restrict__ be, const float* __restrict__ res,
    float* __restrict__ out)
{
    __shared__ float red1[8], red2[8];
    int row = blockIdx.x;
    const float* yr = y + (size_t)row * H_;
    float v[3], sum = 0.0f, sq = 0.0f;
#pragma unroll
    for (int i = 0; i < 3; i++) {
        v[i] = yr[threadIdx.x + 256 * i];
        sum += v[i];
        sq  += v[i] * v[i];
    }
#pragma unroll
    for (int o = 16; o > 0; o >>= 1) {
        sum += __shfl_xor_sync(0xffffffffu, sum, o);
        sq  += __shfl_xor_sync(0xffffffffu, sq,  o);
    }
    int warp = threadIdx.x >> 5;
    if ((threadIdx.x & 31) == 0) { red1[warp] = sum; red2[warp] = sq; }
    __syncthreads();
    float tsum = 0.0f, tsq = 0.0f;
#pragma unroll
    for (int i = 0; i < 8; i++) { tsum += red1[i]; tsq += red2[i]; }
    float mean = tsum * (1.0f / H_);
    float var  = tsq  * (1.0f / H_) - mean * mean;
    float rstd = rsqrtf(var + 1e-5f);
#pragma unroll
    for (int i = 0; i < 3; i++) {
        int c = threadIdx.x + 256 * i;
        float t  = (v[i] - mean) * rstd * g[c] + be[c];
        float ge = 0.5f * t * (1.0f + erff(t * 0.70710678118654752f));
        out[(size_t)row * H_ + c] = (res ? res[(size_t)row * H_ + c] : 0.0f) + ge;
    }
}

// ---------------- final: dot with W3 + bias, empty-line mask, sigmoid ----------------
__global__ __launch_bounds__(128) void final_kernel(
    const float* __restrict__ a2, const float* __restrict__ W3,
    const float* __restrict__ b3, const int* __restrict__ line_lens,
    float* __restrict__ out)
{
    int row  = blockIdx.x * 4 + (threadIdx.x >> 5);
    int lane = threadIdx.x & 31;
    float s = 0.0f;
    for (int c = lane; c < H_; c += 32)
        s += a2[(size_t)row * H_ + c] * W3[c];
#pragma unroll
    for (int o = 16; o > 0; o >>= 1) s += __shfl_xor_sync(0xffffffffu, s, o);
    if (lane == 0) {
        float logit = s + b3[0];
        if (line_lens[row] <= 0) logit = -10.0f;
        out[row] = 1.0f / (1.0f + __expf(-logit));
    }
}

// ---------------- launch ----------------
extern "C" void kernel_launch(void* const* d_in, const int* in_sizes, int n_in,
                              void* d_out, int out_size)
{
    (void)in_sizes; (void)n_in; (void)out_size;
    const float* hidden  = (const float*)d_in[0];
    const float* in_w    = (const float*)d_in[1];
    const float* in_b    = (const float*)d_in[2];
    const float* out_w   = (const float*)d_in[3];
    const float* out_b   = (const float*)d_in[4];
    const float* W1      = (const float*)d_in[5];
    const float* b1      = (const float*)d_in[6];
    const float* g1      = (const float*)d_in[7];
    const float* be1     = (const float*)d_in[8];
    const float* W2      = (const float*)d_in[9];
    const float* b2      = (const float*)d_in[10];
    const float* g2      = (const float*)d_in[11];
    const float* be2     = (const float*)d_in[12];
    const float* W3      = (const float*)d_in[13];
    const float* b3      = (const float*)d_in[14];
    const int*   lstarts = (const int*)d_in[15];
    const int*   llens   = (const int*)d_in[16];
    const int*   ctx     = (const int*)d_in[17];
    float* out = (float*)d_out;

    float *qkv, *attn, *oproj, *x, *y1, *y2;
    cudaGetSymbolAddress((void**)&qkv,   g_qkv);
    cudaGetSymbolAddress((void**)&attn,  g_attn);
    cudaGetSymbolAddress((void**)&oproj, g_oproj);
    cudaGetSymbolAddress((void**)&x,     g_x);
    cudaGetSymbolAddress((void**)&y1,    g_y1);
    cudaGetSymbolAddress((void**)&y2,    g_y2);

    // 1) QKV projection for ALL tokens: [8192,768] @ [2304,768]^T
    sgemm_nt<<<dim3(QKV_ / BN, (B_ * S_) / BM), 256>>>(hidden, in_w, in_b, qkv,
                                                       B_ * S_, QKV_, H_);
    // 2) cross attention (line-token queries over global context)
    attn_kernel<<<dim3(LM_ / QT, NH_, B_), 128>>>(qkv, lstarts, llens, ctx, attn);
    // 3) out_proj: [7680,768] @ [768,768]^T
    sgemm_nt<<<dim3(H_ / BN, (B_ * LM_) / BM), 256>>>(attn, out_w, out_b, oproj,
                                                      B_ * LM_, H_, H_);
    // 4) masked mean-pool -> x [512, 1536]
    pool_kernel<<<B_ * L_, 256>>>(hidden, oproj, lstarts, llens, x);
    // 5) classifier head
    sgemm_nt<<<dim3(H_ / BN, (B_ * L_) / BM), 256>>>(x, W1, b1, y1, B_ * L_, H_, 2 * H_);
    ln_gelu_kernel<<<B_ * L_, 256>>>(y1, g1, be1, nullptr, y1);
    sgemm_nt<<<dim3(H_ / BN, (B_ * L_) / BM), 256>>>(y1, W2, b2, y2, B_ * L_, H_, H_);
    ln_gelu_kernel<<<B_ * L_, 256>>>(y2, g2, be2, y1, y2);
    final_kernel<<<B_ * L_ / 4, 128>>>(y2, W3, b3, llens, out);
}

// round 3
// speedup vs baseline: 1.6169x; 1.6169x over previous
#include <cuda_runtime.h>
#include <math.h>
#include <stdint.h>

// ---------------- problem constants ----------------
#define B_    4
#define S_    2048
#define H_    768
#define NH_   8
#define DH_   96
#define L_    128
#define ML_   15
#define LM_   1920      // L_*ML_
#define QKV_  2304      // 3*H_

// ---------------- scratch ----------------
__device__ float g_qkv  [(size_t)B_ * S_  * QKV_];
__device__ float g_attn [(size_t)B_ * LM_ * H_];
__device__ float g_oproj[(size_t)B_ * LM_ * H_];
__device__ float g_x    [(size_t)B_ * L_ * 2 * H_];
__device__ float g_y1   [(size_t)B_ * L_ * H_];
__device__ float g_y2   [(size_t)B_ * L_ * H_];

// ---------------- tf32 helpers ----------------
__device__ __forceinline__ unsigned f2tf(float x) {
    unsigned r;
    asm("cvt.rna.tf32.f32 %0, %1;" : "=r"(r) : "f"(x));
    return r;
}
__device__ __forceinline__ void mma_tf32(float* d, const unsigned* a, const unsigned* b) {
    asm volatile(
        "mma.sync.aligned.m16n8k8.row.col.f32.tf32.tf32.f32 "
        "{%0,%1,%2,%3}, {%4,%5,%6,%7}, {%8,%9}, {%0,%1,%2,%3};"
        : "+f"(d[0]), "+f"(d[1]), "+f"(d[2]), "+f"(d[3])
        : "r"(a[0]), "r"(a[1]), "r"(a[2]), "r"(a[3]), "r"(b[0]), "r"(b[1]));
}

// ---------------- tf32 NT GEMM: C[M,N] = A[M,K] @ B[N,K]^T + bias ----------------
// Requires: M%128==0, N%128==0, K%32==0. Block 256 thr, tile 128x128x32.
__global__ __launch_bounds__(256) void gemm_tf32_nt(
    const float* __restrict__ A, const float* __restrict__ Bw,
    const float* __restrict__ bias, float* __restrict__ C,
    int M, int N, int K)
{
    // fragment-ordered smem: As[ktile(4)][mtile(8)][lane(32)*4+reg], Bs[ktile(4)][ntile(16)][lane*2+reg]
    __shared__ unsigned As[4 * 8 * 128];
    __shared__ unsigned Bs[4 * 16 * 64];

    int tid = threadIdx.x;
    int warp = tid >> 5, lane = tid & 31;
    int warp_m = warp >> 1, warp_n = warp & 1;
    int m0 = blockIdx.y * 128, n0 = blockIdx.x * 128;

    float acc[2][8][4];
#pragma unroll
    for (int mi = 0; mi < 2; mi++)
#pragma unroll
        for (int ni = 0; ni < 8; ni++)
#pragma unroll
            for (int r = 0; r < 4; r++) acc[mi][ni][r] = 0.0f;

    for (int k0 = 0; k0 < K; k0 += 32) {
        __syncthreads();
        // ---- fill A (128 rows x 32 k) ----
#pragma unroll
        for (int i = 0; i < 4; i++) {
            int f = tid + i * 256;            // 1024 float4s
            int row = f >> 3, kq = f & 7;
            float4 v = *(const float4*)(A + (size_t)(m0 + row) * K + k0 + kq * 4);
            int mtile = row >> 4, r = row & 15, ktile = kq >> 1;
            int regb = (r >> 3) + ((kq & 1) << 1);
            unsigned* p = &As[((ktile * 8 + mtile) * 32 + (r & 7) * 4) * 4 + regb];
            p[0]  = f2tf(v.x);
            p[4]  = f2tf(v.y);
            p[8]  = f2tf(v.z);
            p[12] = f2tf(v.w);
        }
        // ---- fill B (128 rows x 32 k) ----
#pragma unroll
        for (int i = 0; i < 4; i++) {
            int f = tid + i * 256;
            int row = f >> 3, kq = f & 7;
            float4 v = *(const float4*)(Bw + (size_t)(n0 + row) * K + k0 + kq * 4);
            int ntile = row >> 3, ktile = kq >> 1, reg = kq & 1;
            unsigned* p = &Bs[(ktile * 16 + ntile) * 64 + (row & 7) * 8 + reg];
            p[0] = f2tf(v.x);
            p[2] = f2tf(v.y);
            p[4] = f2tf(v.z);
            p[6] = f2tf(v.w);
        }
        __syncthreads();
        // ---- compute ----
#pragma unroll
        for (int ks = 0; ks < 4; ks++) {
            uint4 a[2];
            uint2 b[8];
#pragma unroll
            for (int mi = 0; mi < 2; mi++)
                a[mi] = *(const uint4*)&As[((ks * 8 + warp_m * 2 + mi) * 32 + lane) * 4];
#pragma unroll
            for (int ni = 0; ni < 8; ni++)
                b[ni] = *(const uint2*)&Bs[((ks * 16 + warp_n * 8 + ni) * 32 + lane) * 2];
#pragma unroll
            for (int mi = 0; mi < 2; mi++)
#pragma unroll
                for (int ni = 0; ni < 8; ni++)
                    mma_tf32(acc[mi][ni], (const unsigned*)&a[mi], (const unsigned*)&b[ni]);
        }
    }

    // ---- epilogue ----
#pragma unroll
    for (int mi = 0; mi < 2; mi++) {
        int row = m0 + warp_m * 32 + mi * 16 + (lane >> 2);
#pragma unroll
        for (int ni = 0; ni < 8; ni++) {
            int col = n0 + warp_n * 64 + ni * 8 + ((lane & 3) << 1);
            float b0 = bias ? bias[col] : 0.0f;
            float b1 = bias ? bias[col + 1] : 0.0f;
            float2 lo = make_float2(acc[mi][ni][0] + b0, acc[mi][ni][1] + b1);
            float2 hi = make_float2(acc[mi][ni][2] + b0, acc[mi][ni][3] + b1);
            *(float2*)(C + (size_t)row * N + col)       = lo;
            *(float2*)(C + (size_t)(row + 8) * N + col) = hi;
        }
    }
}

// ---------------- tf32 flash cross-attention ----------------
// grid: (LM/32, NH, B); block 128 threads (4 warps).
#define QT 32
#define KT 64
#define PSP 68   // Ps row stride: 4*row+col covers distinct banks for a-frag loads
__global__ __launch_bounds__(128) void attn_kernel(
    const float* __restrict__ qkv,
    const int* __restrict__ line_starts,
    const int* __restrict__ ctx_len,
    float* __restrict__ out)
{
    // Q frags: [ktile(12)][mtile(2)][lane*4+reg]; KV frags: K=[12][8][64], V=[8][12][64]
    __shared__ unsigned Qs[12 * 2 * 128];
    __shared__ unsigned KVs[6144];
    __shared__ float Ps[QT * PSP];
    __shared__ float m_s[QT], l_s[QT], fac_s[QT];

    int tid = threadIdx.x;
    int warp = tid >> 5, lane = tid & 31;
    int warp_m = warp >> 1;           // scores: m-half (and PV m-half)
    int warp_n = warp & 1;            // scores: n-half / PV: n-half
    int b = blockIdx.z, h = blockIdx.y, q0 = blockIdx.x * QT;
    const float scale = 0.10206207261596577f; // 1/sqrt(96)

    // ---- prologue: gather Q tile, scale, convert, store fragment-order ----
#pragma unroll
    for (int i = 0; i < 6; i++) {
        int f = tid + i * 128;            // 768 float4s = 32 rows * 24
        int row = f / 24, dq = f - row * 24;
        int d0 = dq * 4;
        int gq = q0 + row;
        int l = gq / ML_;
        int m = gq - l * ML_;
        int pos = line_starts[b * L_ + l] + m;
        pos = min(max(pos, 0), S_ - 1);
        float4 v = *(const float4*)(qkv + ((size_t)b * S_ + pos) * QKV_ + h * DH_ + d0);
        int mtile = row >> 4, r = row & 15, ktile = dq >> 1;
        int regb = (r >> 3) + ((dq & 1) << 1);
        unsigned* p = &Qs[(ktile * 2 + mtile) * 128 + ((r & 7) * 4) * 4 + regb];
        p[0]  = f2tf(v.x * scale);
        p[4]  = f2tf(v.y * scale);
        p[8]  = f2tf(v.z * scale);
        p[12] = f2tf(v.w * scale);
    }
    if (tid < QT) { m_s[tid] = -3e38f; l_s[tid] = 0.0f; }
    int ctx = ctx_len[b];
    __syncthreads();

    // each warp holds its Q fragments in registers for the whole loop
    uint4 qf[12];
#pragma unroll
    for (int ks = 0; ks < 12; ks++)
        qf[ks] = *(const uint4*)&Qs[(ks * 2 + warp_m) * 128 + lane * 4];

    float Oacc[6][4];
#pragma unroll
    for (int ni = 0; ni < 6; ni++)
#pragma unroll
        for (int r = 0; r < 4; r++) Oacc[ni][r] = 0.0f;

    int r0 = warp_m * 16 + (lane >> 2);   // this thread's query rows (r0, r0+8)

    for (int s0 = 0; s0 < S_; s0 += KT) {
        __syncthreads();  // prior PV reads of KVs / Ps complete
        // ---- K chunk -> fragment-order smem (B-matrix: n=token, k=dim) ----
#pragma unroll
        for (int i = 0; i < 12; i++) {
            int f = tid + i * 128;          // 1536 float4s = 64 tok * 24
            int token = f / 24, dq = f - token * 24;
            int d0 = dq * 4;
            float4 v = *(const float4*)(qkv + ((size_t)b * S_ + s0 + token) * QKV_ + H_ + h * DH_ + d0);
            int ktile = dq >> 1, ntile = token >> 3, reg = dq & 1;
            unsigned* p = &KVs[(ktile * 8 + ntile) * 64 + (token & 7) * 8 + reg];
            p[0] = f2tf(v.x);
            p[2] = f2tf(v.y);
            p[4] = f2tf(v.z);
            p[6] = f2tf(v.w);
        }
        __syncthreads();

        // ---- scores: warp computes 16(q) x 32(tok) via mma ----
        float sacc[4][4];
#pragma unroll
        for (int ni = 0; ni < 4; ni++)
#pragma unroll
            for (int r = 0; r < 4; r++) sacc[ni][r] = 0.0f;
#pragma unroll
        for (int ks = 0; ks < 12; ks++) {
            uint2 kb[4];
#pragma unroll
            for (int ni = 0; ni < 4; ni++)
                kb[ni] = *(const uint2*)&KVs[((ks * 8 + warp_n * 4 + ni) * 32 + lane) * 2];
#pragma unroll
            for (int ni = 0; ni < 4; ni++)
                mma_tf32(sacc[ni], (const unsigned*)&qf[ks], (const unsigned*)&kb[ni]);
        }
        // masked write to Ps
#pragma unroll
        for (int ni = 0; ni < 4; ni++) {
            int cb = warp_n * 32 + ni * 8 + ((lane & 3) << 1);
            int s_g = s0 + cb;
            Ps[r0 * PSP + cb]           = (s_g     < ctx) ? sacc[ni][0] : -1e9f;
            Ps[r0 * PSP + cb + 1]       = (s_g + 1 < ctx) ? sacc[ni][1] : -1e9f;
            Ps[(r0 + 8) * PSP + cb]     = (s_g     < ctx) ? sacc[ni][2] : -1e9f;
            Ps[(r0 + 8) * PSP + cb + 1] = (s_g + 1 < ctx) ? sacc[ni][3] : -1e9f;
        }
        __syncthreads();

        // ---- online softmax (one quad per query row) + V chunk fill (disjoint) ----
        {
            int row = tid >> 2, sub = tid & 3;
            float mx = -3e38f;
#pragma unroll
            for (int k = sub; k < KT; k += 4) mx = fmaxf(mx, Ps[row * PSP + k]);
            mx = fmaxf(mx, __shfl_xor_sync(0xffffffffu, mx, 1));
            mx = fmaxf(mx, __shfl_xor_sync(0xffffffffu, mx, 2));
            float mold = m_s[row];
            float mnew = fmaxf(mold, mx);
            float lsum = 0.0f;
#pragma unroll
            for (int k = sub; k < KT; k += 4) {
                float p = __expf(Ps[row * PSP + k] - mnew);
                Ps[row * PSP + k] = p;
                lsum += p;
            }
            lsum += __shfl_xor_sync(0xffffffffu, lsum, 1);
            lsum += __shfl_xor_sync(0xffffffffu, lsum, 2);
            if (sub == 0) {
                float fct = __expf(mold - mnew);
                m_s[row]   = mnew;
                l_s[row]   = l_s[row] * fct + lsum;
                fac_s[row] = fct;
            }
        }
        // V chunk -> fragment-order (B-matrix: k=token, n=dim)
#pragma unroll
        for (int i = 0; i < 12; i++) {
            int f = tid + i * 128;
            int token = f / 24, dq = f - token * 24;
            int d0 = dq * 4;
            float4 v = *(const float4*)(qkv + ((size_t)b * S_ + s0 + token) * QKV_ + 2 * H_ + h * DH_ + d0);
            int ktile = token >> 3, ntile = dq >> 1;
            int reg = (token & 4) >> 2;
            int laneb = (d0 & 7) * 4 + (token & 3);
            unsigned* p = &KVs[(ktile * 12 + ntile) * 64 + laneb * 2 + reg];
            p[0] = f2tf(v.x);
            p[8]  = f2tf(v.y);
            p[16] = f2tf(v.z);
            p[24] = f2tf(v.w);
        }
        __syncthreads();

        // ---- rescale + P @ V ----
        float f0 = fac_s[r0], f1 = fac_s[r0 + 8];
#pragma unroll
        for (int ni = 0; ni < 6; ni++) {
            Oacc[ni][0] *= f0; Oacc[ni][1] *= f0;
            Oacc[ni][2] *= f1; Oacc[ni][3] *= f1;
        }
#pragma unroll
        for (int ks = 0; ks < 8; ks++) {
            unsigned pa[4];
            int cb = ks * 8 + (lane & 3);
            pa[0] = f2tf(Ps[r0 * PSP + cb]);
            pa[1] = f2tf(Ps[(r0 + 8) * PSP + cb]);
            pa[2] = f2tf(Ps[r0 * PSP + cb + 4]);
            pa[3] = f2tf(Ps[(r0 + 8) * PSP + cb + 4]);
#pragma unroll
            for (int ni = 0; ni < 6; ni++) {
                uint2 vb = *(const uint2*)&KVs[((ks * 12 + warp_n * 6 + ni) * 32 + lane) * 2];
                mma_tf32(Oacc[ni], pa, (const unsigned*)&vb);
            }
        }
    }

    // ---- epilogue: normalize & store ----
    float inv0 = 1.0f / l_s[r0];
    float inv1 = 1.0f / l_s[r0 + 8];
#pragma unroll
    for (int ni = 0; ni < 6; ni++) {
        int col = h * DH_ + warp_n * 48 + ni * 8 + ((lane & 3) << 1);
        float2 lo = make_float2(Oacc[ni][0] * inv0, Oacc[ni][1] * inv0);
        float2 hi = make_float2(Oacc[ni][2] * inv1, Oacc[ni][3] * inv1);
        *(float2*)(out + ((size_t)b * LM_ + q0 + r0) * H_ + col)     = lo;
        *(float2*)(out + ((size_t)b * LM_ + q0 + r0 + 8) * H_ + col) = hi;
    }
}

// ---------------- masked mean-pool ----------------
__global__ __launch_bounds__(256) void pool_kernel(
    const float* __restrict__ hidden, const float* __restrict__ oproj,
    const int* __restrict__ line_starts, const int* __restrict__ line_lens,
    float* __restrict__ x)
{
    int bl = blockIdx.x;
    int b = bl / L_;
    int len = line_lens[bl];
    int start = line_starts[bl];
    float inv = 1.0f / (float)max(len, 1);
    for (int c = threadIdx.x; c < H_; c += 256) {
        float s1 = 0.0f, s2 = 0.0f;
        for (int m = 0; m < ML_; m++) {
            if (m < len) {
                int pos = min(max(start + m, 0), S_ - 1);
                s1 += hidden[((size_t)b * S_ + pos) * H_ + c];
                s2 += oproj[((size_t)bl * ML_ + m) * H_ + c];
            }
        }
        x[(size_t)bl * 2 * H_ + c]      = s1 * inv;
        x[(size_t)bl * 2 * H_ + H_ + c] = s2 * inv;
    }
}

// ---------------- LayerNorm -> exact GELU (+optional residual) ----------------
__global__ __launch_bounds__(256) void ln_gelu_kernel(
    const float* __restrict__ y, const float* __restrict__ g,
    const float* __restrict__ be, const float* __restrict__ res,
    float* __restrict__ out)
{
    __shared__ float red1[8], red2[8];
    int row = blockIdx.x;
    const float* yr = y + (size_t)row * H_;
    float v[3], sum = 0.0f, sq = 0.0f;
#pragma unroll
    for (int i = 0; i < 3; i++) {
        v[i] = yr[threadIdx.x + 256 * i];
        sum += v[i];
        sq  += v[i] * v[i];
    }
#pragma unroll
    for (int o = 16; o > 0; o >>= 1) {
        sum += __shfl_xor_sync(0xffffffffu, sum, o);
        sq  += __shfl_xor_sync(0xffffffffu, sq,  o);
    }
    int warp = threadIdx.x >> 5;
    if ((threadIdx.x & 31) == 0) { red1[warp] = sum; red2[warp] = sq; }
    __syncthreads();
    float tsum = 0.0f, tsq = 0.0f;
#pragma unroll
    for (int i = 0; i < 8; i++) { tsum += red1[i]; tsq += red2[i]; }
    float mean = tsum * (1.0f / H_);
    float var  = tsq  * (1.0f / H_) - mean * mean;
    float rstd = rsqrtf(var + 1e-5f);
#pragma unroll
    for (int i = 0; i < 3; i++) {
        int c = threadIdx.x + 256 * i;
        float t  = (v[i] - mean) * rstd * g[c] + be[c];
        float ge = 0.5f * t * (1.0f + erff(t * 0.70710678118654752f));
        out[(size_t)row * H_ + c] = (res ? res[(size_t)row * H_ + c] : 0.0f) + ge;
    }
}

// ---------------- final logit ----------------
__global__ __launch_bounds__(128) void final_kernel(
    const float* __restrict__ a2, const float* __restrict__ W3,
    const float* __restrict__ b3, const int* __restrict__ line_lens,
    float* __restrict__ out)
{
    int row  = blockIdx.x * 4 + (threadIdx.x >> 5);
    int lane = threadIdx.x & 31;
    float s = 0.0f;
    for (int c = lane; c < H_; c += 32)
        s += a2[(size_t)row * H_ + c] * W3[c];
#pragma unroll
    for (int o = 16; o > 0; o >>= 1) s += __shfl_xor_sync(0xffffffffu, s, o);
    if (lane == 0) {
        float logit = s + b3[0];
        if (line_lens[row] <= 0) logit = -10.0f;
        out[row] = 1.0f / (1.0f + __expf(-logit));
    }
}

// ---------------- launch ----------------
extern "C" void kernel_launch(void* const* d_in, const int* in_sizes, int n_in,
                              void* d_out, int out_size)
{
    (void)in_sizes; (void)n_in; (void)out_size;
    const float* hidden  = (const float*)d_in[0];
    const float* in_w    = (const float*)d_in[1];
    const float* in_b    = (const float*)d_in[2];
    const float* out_w   = (const float*)d_in[3];
    const float* out_b   = (const float*)d_in[4];
    const float* W1      = (const float*)d_in[5];
    const float* b1      = (const float*)d_in[6];
    const float* g1      = (const float*)d_in[7];
    const float* be1     = (const float*)d_in[8];
    const float* W2      = (const float*)d_in[9];
    const float* b2      = (const float*)d_in[10];
    const float* g2      = (const float*)d_in[11];
    const float* be2     = (const float*)d_in[12];
    const float* W3      = (const float*)d_in[13];
    const float* b3      = (const float*)d_in[14];
    const int*   lstarts = (const int*)d_in[15];
    const int*   llens   = (const int*)d_in[16];
    const int*   ctx     = (const int*)d_in[17];
    float* out = (float*)d_out;

    float *qkv, *attn, *oproj, *x, *y1, *y2;
    cudaGetSymbolAddress((void**)&qkv,   g_qkv);
    cudaGetSymbolAddress((void**)&attn,  g_attn);
    cudaGetSymbolAddress((void**)&oproj, g_oproj);
    cudaGetSymbolAddress((void**)&x,     g_x);
    cudaGetSymbolAddress((void**)&y1,    g_y1);
    cudaGetSymbolAddress((void**)&y2,    g_y2);

    // 1) QKV projection: [8192,2304] = [8192,768] @ [2304,768]^T
    gemm_tf32_nt<<<dim3(QKV_ / 128, (B_ * S_) / 128), 256>>>(hidden, in_w, in_b, qkv,
                                                             B_ * S_, QKV_, H_);
    // 2) cross attention
    attn_kernel<<<dim3(LM_ / QT, NH_, B_), 128>>>(qkv, lstarts, ctx, attn);
    // 3) out_proj: [7680,768] @ [768,768]^T
    gemm_tf32_nt<<<dim3(H_ / 128, (B_ * LM_) / 128), 256>>>(attn, out_w, out_b, oproj,
                                                            B_ * LM_, H_, H_);
    // 4) pooled features
    pool_kernel<<<B_ * L_, 256>>>(hidden, oproj, lstarts, llens, x);
    // 5) classifier head
    gemm_tf32_nt<<<dim3(H_ / 128, (B_ * L_) / 128), 256>>>(x, W1, b1, y1, B_ * L_, H_, 2 * H_);
    ln_gelu_kernel<<<B_ * L_, 256>>>(y1, g1, be1, nullptr, y1);
    gemm_tf32_nt<<<dim3(H_ / 128, (B_ * L_) / 128), 256>>>(y1, W2, b2, y2, B_ * L_, H_, H_);
    ln_gelu_kernel<<<B_ * L_, 256>>>(y2, g2, be2, y1, y2);
    final_kernel<<<B_ * L_ / 4, 128>>>(y2, W3, b3, llens, out);
}